// round 5
// baseline (speedup 1.0000x reference)
#include <cuda_runtime.h>

#define FULLMASK 0xFFFFFFFFu

__device__ float g_A[1024 * 512];
__device__ float g_Rt[8 * 512];
__device__ float g_partial[2048 * 512];
__device__ float g_img[16 * 512];
__device__ float g_emb[16 * 1024];
__device__ float g_hidden[16 * 512];

#define XS 36
#define SMEM_FLOATS (512 * XS * 2 + 8 * 512)
#define SMEM_BYTES (SMEM_FLOATS * 4)

// GEMM layer: out[o][j] = relu(bias[o] + sum_k Xs[k][j] * W[o][k])
template <bool LAST>
__device__ __forceinline__ void layer(const float* __restrict__ W,
                                      const float* __restrict__ bias,
                                      const float* Xs, float* Xd, float* Ws,
                                      float* partial) {
    const int tid = threadIdx.x, ty = tid >> 5, tx = tid & 31;
    const int jb = ty * 4;
    float acc[4][16];
#pragma unroll
    for (int p = 0; p < 4; p++)
#pragma unroll
        for (int u = 0; u < 16; u++) acc[p][u] = 0.f;

    for (int kc = 0; kc < 64; kc++) {
        __syncthreads();
        // stage W tile: Ws[kk][o] = W[o][kc*8+kk]
#pragma unroll
        for (int s = 0; s < 2; s++) {
            int o = tid * 2 + s;
            float4 wa = *(const float4*)(W + o * 512 + kc * 8);
            float4 wb = *(const float4*)(W + o * 512 + kc * 8 + 4);
            Ws[0 * 512 + o] = wa.x; Ws[1 * 512 + o] = wa.y;
            Ws[2 * 512 + o] = wa.z; Ws[3 * 512 + o] = wa.w;
            Ws[4 * 512 + o] = wb.x; Ws[5 * 512 + o] = wb.y;
            Ws[6 * 512 + o] = wb.z; Ws[7 * 512 + o] = wb.w;
        }
        __syncthreads();
#pragma unroll
        for (int kk = 0; kk < 8; kk++) {
            float4 xv = *(const float4*)(Xs + (kc * 8 + kk) * XS + jb);
#pragma unroll
            for (int u = 0; u < 16; u++) {
                float w = Ws[kk * 512 + tx + 32 * u];
                acc[0][u] = fmaf(xv.x, w, acc[0][u]);
                acc[1][u] = fmaf(xv.y, w, acc[1][u]);
                acc[2][u] = fmaf(xv.z, w, acc[2][u]);
                acc[3][u] = fmaf(xv.w, w, acc[3][u]);
            }
        }
    }
    __syncthreads();
    if (!LAST) {
#pragma unroll
        for (int u = 0; u < 16; u++) {
            int o = tx + 32 * u;
            float bv = bias[o];
#pragma unroll
            for (int p = 0; p < 4; p++)
                Xd[o * XS + jb + p] = fmaxf(acc[p][u] + bv, 0.f);
        }
    } else {
        // per-warp sums into Ws[ty][o], then cross-warp reduce
#pragma unroll
        for (int u = 0; u < 16; u++) {
            int o = tx + 32 * u;
            float bv = bias[o], s = 0.f;
#pragma unroll
            for (int p = 0; p < 4; p++) s += fmaxf(acc[p][u] + bv, 0.f);
            Ws[ty * 512 + o] = s;
        }
        __syncthreads();
#pragma unroll
        for (int oo = 0; oo < 2; oo++) {
            int o = tid + 256 * oo;
            float t = 0.f;
#pragma unroll
            for (int w = 0; w < 8; w++) t += Ws[w * 512 + o];
            partial[o] = t;
        }
    }
}

__global__ void __launch_bounds__(256, 1)
main_kernel(const float* __restrict__ input, const float* __restrict__ W2,
            const float* __restrict__ b2, const float* __restrict__ W3,
            const float* __restrict__ b3) {
    extern __shared__ float sm[];
    float* X1 = sm;
    float* X2 = X1 + 512 * XS;
    float* Ws = X2 + 512 * XS;  // also used as xin during h1
    const int cta = blockIdx.x;
    const int b = cta >> 7, rem = cta & 127;
    const int i = rem >> 1, j0 = (rem & 1) * 32;
    const int tid = threadIdx.x;

    float* xin = Ws;
    xin[tid] = input[(b * 64 + i) * 512 + j0 * 8 + tid];
    __syncthreads();

    // h1: X1[o][j] = relu(A[b,j0+j,o] + sum_m xin[8j+m]*Rt[m,o])
#pragma unroll
    for (int oo = 0; oo < 2; oo++) {
        int o = tid + 256 * oo;
        float r[8];
#pragma unroll
        for (int m = 0; m < 8; m++) r[m] = g_Rt[m * 512 + o];
        const float* Ab = g_A + (b * 64 + j0) * 512 + o;
#pragma unroll 4
        for (int j = 0; j < 32; j++) {
            float s = Ab[j * 512];
#pragma unroll
            for (int m = 0; m < 8; m++) s = fmaf(xin[j * 8 + m], r[m], s);
            X1[o * XS + j] = fmaxf(s, 0.f);
        }
    }
    layer<false>(W2, b2, X1, X2, Ws, nullptr);
    layer<true>(W3, b3, X2, nullptr, Ws, g_partial + cta * 512);
}

// A = input_flat[1024x512] @ W1[:, :512].T + b1
__global__ void prep_a_kernel(const float* __restrict__ X,
                              const float* __restrict__ W1,
                              const float* __restrict__ b1) {
    __shared__ float As[16][68];
    __shared__ float Bs[16][68];
    const int tid = threadIdx.x;
    const int row0 = blockIdx.x * 64, col0 = blockIdx.y * 64;
    const int tx = tid & 15, ty = tid >> 4;
    float acc[4][4] = {};
    for (int kc = 0; kc < 32; kc++) {
#pragma unroll
        for (int s = 0; s < 4; s++) {
            int idx = tid + s * 256;
            int m = idx >> 4, kk = idx & 15;
            As[kk][m] = X[(row0 + m) * 512 + kc * 16 + kk];
            Bs[kk][m] = W1[(col0 + m) * 1024 + kc * 16 + kk];
        }
        __syncthreads();
#pragma unroll
        for (int kk = 0; kk < 16; kk++) {
            float a[4], bb[4];
#pragma unroll
            for (int u = 0; u < 4; u++) a[u] = As[kk][ty * 4 + u];
#pragma unroll
            for (int u = 0; u < 4; u++) bb[u] = Bs[kk][tx * 4 + u];
#pragma unroll
            for (int u = 0; u < 4; u++)
#pragma unroll
                for (int v = 0; v < 4; v++)
                    acc[u][v] = fmaf(a[u], bb[v], acc[u][v]);
        }
        __syncthreads();
    }
#pragma unroll
    for (int u = 0; u < 4; u++) {
        int row = row0 + ty * 4 + u;
#pragma unroll
        for (int v = 0; v < 4; v++) {
            int o = col0 + tx * 4 + v;
            g_A[row * 512 + o] = acc[u][v] + b1[o];
        }
    }
}

__global__ void prep_r_kernel(const float* __restrict__ W1) {
    int o = threadIdx.x, m = blockIdx.x;
    const float* p = W1 + o * 1024 + 512 + m * 64;
    float s = 0.f;
#pragma unroll
    for (int t = 0; t < 64; t++) s += p[t];
    g_Rt[m * 512 + o] = s;
}

__global__ void reduce_sent_kernel() {
    int b = blockIdx.x, o = threadIdx.x;
    const float* p = g_partial + b * 128 * 512 + o;
    float s = 0.f;
#pragma unroll 8
    for (int q = 0; q < 128; q++) s += p[q * 512];
    g_emb[b * 1024 + o] = s * (1.0f / 4096.0f);
}

__global__ void im_gemm_kernel(const float* __restrict__ imx,
                               const float* __restrict__ imw,
                               const float* __restrict__ imb) {
    int gw = (blockIdx.x * blockDim.x + threadIdx.x) >> 5;
    int lane = threadIdx.x & 31;
    int bi = gw >> 9, o = gw & 511;
    const float* x = imx + bi * 2048;
    const float* wv = imw + o * 2048;
    float s = 0.f;
    for (int k = lane; k < 2048; k += 32) s = fmaf(x[k], wv[k], s);
#pragma unroll
    for (int d = 16; d; d >>= 1) s += __shfl_xor_sync(FULLMASK, s, d);
    if (lane == 0) g_img[bi * 512 + o] = s + imb[o];
}

__global__ void bn_relu_kernel(const float* __restrict__ gamma,
                               const float* __restrict__ beta) {
    int o = threadIdx.x;
    float v[16], mu = 0.f;
#pragma unroll
    for (int bi = 0; bi < 16; bi++) { v[bi] = g_img[bi * 512 + o]; mu += v[bi]; }
    mu *= (1.f / 16.f);
    float var = 0.f;
#pragma unroll
    for (int bi = 0; bi < 16; bi++) { float d = v[bi] - mu; var = fmaf(d, d, var); }
    var *= (1.f / 16.f);
    float inv = rsqrtf(var + 1e-5f);
    float g = gamma[o], be = beta[o];
#pragma unroll
    for (int bi = 0; bi < 16; bi++) {
        float y = fmaf(g * (v[bi] - mu), inv, be);
        g_emb[bi * 1024 + 512 + o] = fmaxf(y, 0.f);
    }
}

__global__ void head1_kernel(const float* __restrict__ d1w,
                             const float* __restrict__ d1b) {
    int gw = (blockIdx.x * blockDim.x + threadIdx.x) >> 5;
    int lane = threadIdx.x & 31;
    int bi = gw >> 9, o = gw & 511;
    const float* e = g_emb + bi * 1024;
    const float* wv = d1w + o * 1024;
    float s = 0.f;
    for (int k = lane; k < 1024; k += 32) s = fmaf(e[k], wv[k], s);
#pragma unroll
    for (int d = 16; d; d >>= 1) s += __shfl_xor_sync(FULLMASK, s, d);
    if (lane == 0) g_hidden[bi * 512 + o] = fmaxf(s + d1b[o], 0.f);
}

__global__ void head2_kernel(const float* __restrict__ d2w,
                             const float* __restrict__ d2b,
                             float* __restrict__ out) {
    int gw = threadIdx.x >> 5, lane = threadIdx.x & 31;
    int bi = gw >> 1, q = gw & 1;
    const float* h = g_hidden + bi * 512;
    const float* wv = d2w + q * 512;
    float s = 0.f;
    for (int k = lane; k < 512; k += 32) s = fmaf(h[k], wv[k], s);
#pragma unroll
    for (int d = 16; d; d >>= 1) s += __shfl_xor_sync(FULLMASK, s, d);
    if (lane == 0) out[bi * 2 + q] = s + d2b[q];
}

extern "C" void kernel_launch(void* const* d_in, const int* in_sizes, int n_in,
                              void* d_out, int out_size) {
    const float* input = (const float*)d_in[0];
    const float* im_input = (const float*)d_in[1];
    const float* g1w = (const float*)d_in[2];
    const float* g1b = (const float*)d_in[3];
    const float* g2w = (const float*)d_in[4];
    const float* g2b = (const float*)d_in[5];
    const float* g3w = (const float*)d_in[6];
    const float* g3b = (const float*)d_in[7];
    const float* imw = (const float*)d_in[8];
    const float* imb = (const float*)d_in[9];
    const float* gam = (const float*)d_in[10];
    const float* bet = (const float*)d_in[11];
    const float* d1w = (const float*)d_in[12];
    const float* d1b = (const float*)d_in[13];
    const float* d2w = (const float*)d_in[14];
    const float* d2b = (const float*)d_in[15];
    float* out = (float*)d_out;

    cudaFuncSetAttribute(main_kernel,
                         cudaFuncAttributeMaxDynamicSharedMemorySize, SMEM_BYTES);

    prep_a_kernel<<<dim3(16, 8), 256>>>(input, g1w, g1b);
    prep_r_kernel<<<8, 512>>>(g1w);
    main_kernel<<<2048, 256, SMEM_BYTES>>>(input, g2w, g2b, g3w, g3b);
    reduce_sent_kernel<<<16, 512>>>();
    im_gemm_kernel<<<1024, 256>>>(im_input, imw, imb);
    bn_relu_kernel<<<1, 512>>>(gam, bet);
    head1_kernel<<<1024, 256>>>(d1w, d1b);
    head2_kernel<<<1, 1024>>>(d2w, d2b, out);
}

// round 7
// speedup vs baseline: 1.2848x; 1.2848x over previous
#include <cuda_runtime.h>

#define FULLMASK 0xFFFFFFFFu
typedef unsigned long long u64;

__device__ float g_A[1024 * 512];
__device__ float g_Rt[8 * 512];
__device__ float g_W2t[512 * 512];
__device__ float g_W3t[512 * 512];
__device__ float g_partial[2048 * 512];
__device__ float g_img[16 * 512];
__device__ float g_emb[16 * 1024];
__device__ float g_hidden[16 * 512];

#define XS 36
#define SMEM_FLOATS (512 * XS * 2 + 2 * 8 * 512)
#define SMEM_BYTES (SMEM_FLOATS * 4)

__device__ __forceinline__ u64 pk2(float x, float y) {
    u64 r; asm("mov.b64 %0, {%1,%2};" : "=l"(r) : "f"(x), "f"(y)); return r;
}
__device__ __forceinline__ void upk2(u64 v, float& x, float& y) {
    asm("mov.b64 {%0,%1}, %2;" : "=f"(x), "=f"(y) : "l"(v));
}
__device__ __forceinline__ void ffma2(u64& d, u64 a, u64 b) {
    asm("fma.rn.f32x2 %0, %1, %2, %0;" : "+l"(d) : "l"(a), "l"(b));
}

// out[o][j] = relu(bias[o] + sum_k Xs[k][j] * Wt[k][o]); Wt is [512 k][512 o]
template <bool LAST>
__device__ __forceinline__ void layer(const float* __restrict__ Wt,
                                      const float* __restrict__ bias,
                                      const float* Xs, float* Xd, float* Ws,
                                      float* partial) {
    const int tid = threadIdx.x;
    const int w = tid >> 5, tx = tid & 31;
    const int og = w & 1, jg = w >> 2;        // wait: need 2 og * 4 jg
    const int jgr = (w >> 1);                  // 0..3
    const int jb = jgr * 8;
    const int obase = og * 256 + 2 * tx;       // o pairs at obase + 64*c

    u64 acc[4][8];
#pragma unroll
    for (int c = 0; c < 4; c++)
#pragma unroll
        for (int p = 0; p < 8; p++) acc[c][p] = 0ull;

    const u64 unused = (u64)jg; (void)unused;

    auto stage = [&](int kc, int bsel) {
        const float4* src = (const float4*)(Wt + kc * 8 * 512);
        unsigned dst = (unsigned)__cvta_generic_to_shared(Ws + bsel * 4096);
#pragma unroll
        for (int s = 0; s < 4; s++) {
            int f = tid + 256 * s;
            asm volatile("cp.async.cg.shared.global [%0], [%1], 16;"
                         :: "r"(dst + f * 16), "l"(src + f));
        }
        asm volatile("cp.async.commit_group;");
    };

    stage(0, 0);
    stage(1, 1);

    for (int kc = 0; kc < 64; kc++) {
        if (kc < 63) asm volatile("cp.async.wait_group 1;");
        else         asm volatile("cp.async.wait_group 0;");
        __syncthreads();
        const float* buf = Ws + (kc & 1) * 4096;
#pragma unroll
        for (int kk = 0; kk < 8; kk++) {
            const float* row = buf + kk * 512;
            const float* xr = Xs + (kc * 8 + kk) * XS + jb;
            float4 xa = *(const float4*)xr;
            float4 xb = *(const float4*)(xr + 4);
            u64 xp[8];
            xp[0] = pk2(xa.x, xa.x); xp[1] = pk2(xa.y, xa.y);
            xp[2] = pk2(xa.z, xa.z); xp[3] = pk2(xa.w, xa.w);
            xp[4] = pk2(xb.x, xb.x); xp[5] = pk2(xb.y, xb.y);
            xp[6] = pk2(xb.z, xb.z); xp[7] = pk2(xb.w, xb.w);
            u64 wv[4];
#pragma unroll
            for (int c = 0; c < 4; c++)
                wv[c] = *(const u64*)(row + obase + 64 * c);
#pragma unroll
            for (int c = 0; c < 4; c++)
#pragma unroll
                for (int p = 0; p < 8; p++) ffma2(acc[c][p], wv[c], xp[p]);
        }
        __syncthreads();
        if (kc + 2 < 64) stage(kc + 2, kc & 1);
    }

    if (!LAST) {
#pragma unroll
        for (int c = 0; c < 4; c++) {
            int o0 = obase + 64 * c;
            float b0 = bias[o0], b1 = bias[o0 + 1];
#pragma unroll
            for (int p = 0; p < 8; p++) {
                float v0, v1; upk2(acc[c][p], v0, v1);
                Xd[o0 * XS + jb + p]       = fmaxf(v0 + b0, 0.f);
                Xd[(o0 + 1) * XS + jb + p] = fmaxf(v1 + b1, 0.f);
            }
        }
    } else {
#pragma unroll
        for (int c = 0; c < 4; c++) {
            int o0 = obase + 64 * c;
            float b0 = bias[o0], b1 = bias[o0 + 1];
            float s0 = 0.f, s1 = 0.f;
#pragma unroll
            for (int p = 0; p < 8; p++) {
                float v0, v1; upk2(acc[c][p], v0, v1);
                s0 += fmaxf(v0 + b0, 0.f);
                s1 += fmaxf(v1 + b1, 0.f);
            }
            *(float2*)(Ws + jgr * 512 + o0) = make_float2(s0, s1);
        }
        __syncthreads();
#pragma unroll
        for (int oo = 0; oo < 2; oo++) {
            int o = tid + 256 * oo;
            float t = 0.f;
#pragma unroll
            for (int g = 0; g < 4; g++) t += Ws[g * 512 + o];
            partial[o] = t;
        }
    }
}

__global__ void __launch_bounds__(256, 1)
main_kernel(const float* __restrict__ input, const float* __restrict__ b2,
            const float* __restrict__ b3) {
    extern __shared__ float sm[];
    float* X1 = sm;
    float* X2 = X1 + 512 * XS;
    float* Ws = X2 + 512 * XS;
    const int cta = blockIdx.x;
    const int b = cta >> 7, rem = cta & 127;
    const int i = rem >> 1, j0 = (rem & 1) * 32;
    const int tid = threadIdx.x;

    float* xin = Ws;
    xin[tid] = input[(b * 64 + i) * 512 + j0 * 8 + tid];
    __syncthreads();

    // h1: X1[o][j] = relu(A[b,j0+j,o] + sum_m xin[8j+m]*Rt[m,o])
#pragma unroll
    for (int oo = 0; oo < 2; oo++) {
        int o = tid + 256 * oo;
        float r[8];
#pragma unroll
        for (int m = 0; m < 8; m++) r[m] = g_Rt[m * 512 + o];
        const float* Ab = g_A + (b * 64 + j0) * 512 + o;
#pragma unroll 4
        for (int j = 0; j < 32; j++) {
            float s = Ab[j * 512];
#pragma unroll
            for (int m = 0; m < 8; m++) s = fmaf(xin[j * 8 + m], r[m], s);
            X1[o * XS + j] = fmaxf(s, 0.f);
        }
    }
    __syncthreads();  // xin (in Ws) consumed before layer2 stages into Ws

    layer<false>(g_W2t, b2, X1, X2, Ws, nullptr);
    layer<true >(g_W3t, b3, X2, nullptr, Ws, g_partial + cta * 512);
}

__global__ void transpose_kernel(const float* __restrict__ W,
                                 float* __restrict__ Wt) {
    __shared__ float t[32][33];
    int x = blockIdx.x * 32 + threadIdx.x;
    int y0 = blockIdx.y * 32;
#pragma unroll
    for (int s = 0; s < 32; s += 8)
        t[threadIdx.y + s][threadIdx.x] = W[(y0 + threadIdx.y + s) * 512 + x];
    __syncthreads();
    int xo = blockIdx.y * 32 + threadIdx.x;
    int yo0 = blockIdx.x * 32;
#pragma unroll
    for (int s = 0; s < 32; s += 8)
        Wt[(yo0 + threadIdx.y + s) * 512 + xo] = t[threadIdx.x][threadIdx.y + s];
}

__global__ void prep_a_kernel(const float* __restrict__ X,
                              const float* __restrict__ W1,
                              const float* __restrict__ b1) {
    __shared__ float As[16][68];
    __shared__ float Bs[16][68];
    const int tid = threadIdx.x;
    const int row0 = blockIdx.x * 64, col0 = blockIdx.y * 64;
    const int tx = tid & 15, ty = tid >> 4;
    float acc[4][4] = {};
    for (int kc = 0; kc < 32; kc++) {
#pragma unroll
        for (int s = 0; s < 4; s++) {
            int idx = tid + s * 256;
            int m = idx >> 4, kk = idx & 15;
            As[kk][m] = X[(row0 + m) * 512 + kc * 16 + kk];
            Bs[kk][m] = W1[(col0 + m) * 1024 + kc * 16 + kk];
        }
        __syncthreads();
#pragma unroll
        for (int kk = 0; kk < 16; kk++) {
            float a[4], bb[4];
#pragma unroll
            for (int u = 0; u < 4; u++) a[u] = As[kk][ty * 4 + u];
#pragma unroll
            for (int u = 0; u < 4; u++) bb[u] = Bs[kk][tx * 4 + u];
#pragma unroll
            for (int u = 0; u < 4; u++)
#pragma unroll
                for (int v = 0; v < 4; v++)
                    acc[u][v] = fmaf(a[u], bb[v], acc[u][v]);
        }
        __syncthreads();
    }
#pragma unroll
    for (int u = 0; u < 4; u++) {
        int row = row0 + ty * 4 + u;
#pragma unroll
        for (int v = 0; v < 4; v++) {
            int o = col0 + tx * 4 + v;
            g_A[row * 512 + o] = acc[u][v] + b1[o];
        }
    }
}

__global__ void prep_r_kernel(const float* __restrict__ W1) {
    int o = threadIdx.x, m = blockIdx.x;
    const float* p = W1 + o * 1024 + 512 + m * 64;
    float s = 0.f;
#pragma unroll
    for (int t = 0; t < 64; t++) s += p[t];
    g_Rt[m * 512 + o] = s;
}

__global__ void reduce_sent_kernel() {
    int b = blockIdx.x, o = threadIdx.x;
    const float* p = g_partial + b * 128 * 512 + o;
    float s = 0.f;
#pragma unroll 8
    for (int q = 0; q < 128; q++) s += p[q * 512];
    g_emb[b * 1024 + o] = s * (1.0f / 4096.0f);
}

__global__ void im_gemm_kernel(const float* __restrict__ imx,
                               const float* __restrict__ imw,
                               const float* __restrict__ imb) {
    int gw = (blockIdx.x * blockDim.x + threadIdx.x) >> 5;
    int lane = threadIdx.x & 31;
    int bi = gw >> 9, o = gw & 511;
    const float* x = imx + bi * 2048;
    const float* wv = imw + o * 2048;
    float s = 0.f;
    for (int k = lane; k < 2048; k += 32) s = fmaf(x[k], wv[k], s);
#pragma unroll
    for (int d = 16; d; d >>= 1) s += __shfl_xor_sync(FULLMASK, s, d);
    if (lane == 0) g_img[bi * 512 + o] = s + imb[o];
}

__global__ void bn_relu_kernel(const float* __restrict__ gamma,
                               const float* __restrict__ beta) {
    int o = threadIdx.x;
    float v[16], mu = 0.f;
#pragma unroll
    for (int bi = 0; bi < 16; bi++) { v[bi] = g_img[bi * 512 + o]; mu += v[bi]; }
    mu *= (1.f / 16.f);
    float var = 0.f;
#pragma unroll
    for (int bi = 0; bi < 16; bi++) { float d = v[bi] - mu; var = fmaf(d, d, var); }
    var *= (1.f / 16.f);
    float inv = rsqrtf(var + 1e-5f);
    float g = gamma[o], be = beta[o];
#pragma unroll
    for (int bi = 0; bi < 16; bi++) {
        float y = fmaf(g * (v[bi] - mu), inv, be);
        g_emb[bi * 1024 + 512 + o] = fmaxf(y, 0.f);
    }
}

__global__ void head1_kernel(const float* __restrict__ d1w,
                             const float* __restrict__ d1b) {
    int gw = (blockIdx.x * blockDim.x + threadIdx.x) >> 5;
    int lane = threadIdx.x & 31;
    int bi = gw >> 9, o = gw & 511;
    const float* e = g_emb + bi * 1024;
    const float* wv = d1w + o * 1024;
    float s = 0.f;
    for (int k = lane; k < 1024; k += 32) s = fmaf(e[k], wv[k], s);
#pragma unroll
    for (int d = 16; d; d >>= 1) s += __shfl_xor_sync(FULLMASK, s, d);
    if (lane == 0) g_hidden[bi * 512 + o] = fmaxf(s + d1b[o], 0.f);
}

__global__ void head2_kernel(const float* __restrict__ d2w,
                             const float* __restrict__ d2b,
                             float* __restrict__ out) {
    int gw = threadIdx.x >> 5, lane = threadIdx.x & 31;
    int bi = gw >> 1, q = gw & 1;
    const float* h = g_hidden + bi * 512;
    const float* wv = d2w + q * 512;
    float s = 0.f;
    for (int k = lane; k < 512; k += 32) s = fmaf(h[k], wv[k], s);
#pragma unroll
    for (int d = 16; d; d >>= 1) s += __shfl_xor_sync(FULLMASK, s, d);
    if (lane == 0) out[bi * 2 + q] = s + d2b[q];
}

extern "C" void kernel_launch(void* const* d_in, const int* in_sizes, int n_in,
                              void* d_out, int out_size) {
    const float* input = (const float*)d_in[0];
    const float* im_input = (const float*)d_in[1];
    const float* g1w = (const float*)d_in[2];
    const float* g1b = (const float*)d_in[3];
    const float* g2w = (const float*)d_in[4];
    const float* g2b = (const float*)d_in[5];
    const float* g3w = (const float*)d_in[6];
    const float* g3b = (const float*)d_in[7];
    const float* imw = (const float*)d_in[8];
    const float* imb = (const float*)d_in[9];
    const float* gam = (const float*)d_in[10];
    const float* bet = (const float*)d_in[11];
    const float* d1w = (const float*)d_in[12];
    const float* d1b = (const float*)d_in[13];
    const float* d2w = (const float*)d_in[14];
    const float* d2b = (const float*)d_in[15];
    float* out = (float*)d_out;

    cudaFuncSetAttribute(main_kernel,
                         cudaFuncAttributeMaxDynamicSharedMemorySize, SMEM_BYTES);

    float* w2t; cudaGetSymbolAddress((void**)&w2t, g_W2t);
    float* w3t; cudaGetSymbolAddress((void**)&w3t, g_W3t);

    prep_a_kernel<<<dim3(16, 8), 256>>>(input, g1w, g1b);
    prep_r_kernel<<<8, 512>>>(g1w);
    transpose_kernel<<<dim3(16, 16), dim3(32, 8)>>>(g2w, w2t);
    transpose_kernel<<<dim3(16, 16), dim3(32, 8)>>>(g3w, w3t);
    main_kernel<<<2048, 256, SMEM_BYTES>>>(input, g2b, g3b);
    reduce_sent_kernel<<<16, 512>>>();
    im_gemm_kernel<<<1024, 256>>>(im_input, imw, imb);
    bn_relu_kernel<<<1, 512>>>(gam, bet);
    head1_kernel<<<1024, 256>>>(d1w, d1b);
    head2_kernel<<<1, 1024>>>(d2w, d2b, out);
}

// round 9
// speedup vs baseline: 8.0521x; 6.2670x over previous
#include <cuda_runtime.h>
#include <cuda_fp16.h>
#include <cstdint>

#define FULLMASK 0xFFFFFFFFu

__device__ float  g_A[1024 * 512];
__device__ float  g_Rt[8 * 512];
__device__ __half g_W2t[512 * 512];   // f16, transposed: [k][o]
__device__ __half g_W3t[512 * 512];
__device__ float  g_partial[1024 * 512];
__device__ float  g_img[16 * 512];
__device__ float  g_emb[16 * 1024];
__device__ float  g_hidden[16 * 512];

// smem layout (bytes): X1 [64][520]f16, X2 [64][520]f16, 3x W stage [16][520]f16
#define XPITCH 1040
#define SM_X1 0
#define SM_X2 66560
#define SM_WB 133120
#define WBSZ  16640
#define SMEM_TOTAL 183040

__device__ __forceinline__ void ldsm4(uint32_t* r, uint32_t a) {
    asm volatile("ldmatrix.sync.aligned.m8n8.x4.shared.b16 {%0,%1,%2,%3}, [%4];"
                 : "=r"(r[0]), "=r"(r[1]), "=r"(r[2]), "=r"(r[3]) : "r"(a));
}
__device__ __forceinline__ void ldsm4t(uint32_t* r, uint32_t a) {
    asm volatile("ldmatrix.sync.aligned.m8n8.x4.trans.shared.b16 {%0,%1,%2,%3}, [%4];"
                 : "=r"(r[0]), "=r"(r[1]), "=r"(r[2]), "=r"(r[3]) : "r"(a));
}
__device__ __forceinline__ void mma16816(float* c, const uint32_t* a,
                                         uint32_t b0, uint32_t b1) {
    asm volatile(
        "mma.sync.aligned.m16n8k16.row.col.f32.f16.f16.f32 "
        "{%0,%1,%2,%3}, {%4,%5,%6,%7}, {%8,%9}, {%0,%1,%2,%3};"
        : "+f"(c[0]), "+f"(c[1]), "+f"(c[2]), "+f"(c[3])
        : "r"(a[0]), "r"(a[1]), "r"(a[2]), "r"(a[3]), "r"(b0), "r"(b1));
}

// stage 16 k-rows of Wt[k][512] f16 into ring buffer s%3
__device__ __forceinline__ void stageW(const __half* Wt, int s, uint32_t smem,
                                       int tid) {
    const char* src = (const char*)(Wt + (size_t)s * 16 * 512);
    uint32_t dst = smem + SM_WB + (s % 3) * WBSZ;
#pragma unroll
    for (int q = 0; q < 4; q++) {
        int idx = tid + q * 256;
        int row = idx >> 6, c = idx & 63;
        asm volatile("cp.async.cg.shared.global [%0], [%1], 16;"
                     :: "r"(dst + row * XPITCH + c * 16),
                        "l"(src + row * 1024 + c * 16));
    }
    asm volatile("cp.async.commit_group;" ::: "memory");
}

// C[64 x 512] = A(smem f16, pitch 1040) * W(streamed); !LAST: ->X2 f16; LAST: column sums -> red
template <bool LAST>
__device__ __forceinline__ void gemm_layer(char* smb, uint32_t smem, uint32_t smA,
                                           const __half* Wt, const __half* nextWt,
                                           const float* __restrict__ bias, int tid) {
    const int lane = tid & 31, w = tid >> 5;
    const int wm = (w >> 2) * 32, wn = (w & 3) * 128;
    float acc[2][16][4];
#pragma unroll
    for (int mt = 0; mt < 2; mt++)
#pragma unroll
        for (int nt = 0; nt < 16; nt++)
#pragma unroll
            for (int e = 0; e < 4; e++) acc[mt][nt][e] = 0.f;

    const uint32_t aAddr0 = smA + (wm + (lane & 15)) * XPITCH + (lane >> 4) * 16;
    const uint32_t aAddr1 = aAddr0 + 16 * XPITCH;
    const uint32_t bOff = (lane & 15) * XPITCH + (lane >> 4) * 16 + wn * 2;

#pragma unroll 1
    for (int s = 0; s < 32; s++) {
        if (s < 31) asm volatile("cp.async.wait_group 1;" ::: "memory");
        else        asm volatile("cp.async.wait_group 0;" ::: "memory");
        __syncthreads();
        uint32_t bb = smem + SM_WB + (s % 3) * WBSZ + bOff;
        uint32_t a0[4], a1[4];
        ldsm4(a0, aAddr0 + s * 32);
        ldsm4(a1, aAddr1 + s * 32);
#pragma unroll
        for (int ng = 0; ng < 8; ng++) {
            uint32_t bf[4];
            ldsm4t(bf, bb + ng * 32);
            mma16816(acc[0][2 * ng],     a0, bf[0], bf[1]);
            mma16816(acc[0][2 * ng + 1], a0, bf[2], bf[3]);
            mma16816(acc[1][2 * ng],     a1, bf[0], bf[1]);
            mma16816(acc[1][2 * ng + 1], a1, bf[2], bf[3]);
        }
        if (s + 2 < 32) stageW(Wt, s + 2, smem, tid);
    }
    __syncthreads();
    if (nextWt) { stageW(nextWt, 0, smem, tid); stageW(nextWt, 1, smem, tid); }

    if (!LAST) {
#pragma unroll
        for (int mt = 0; mt < 2; mt++) {
            int row0 = wm + mt * 16 + (lane >> 2);
#pragma unroll
            for (int nt = 0; nt < 16; nt++) {
                int col = wn + nt * 8 + (lane & 3) * 2;
                float b0 = __ldg(bias + col), b1 = __ldg(bias + col + 1);
                float* c = acc[mt][nt];
                __half2 h0 = __floats2half2_rn(fmaxf(c[0] + b0, 0.f),
                                               fmaxf(c[1] + b1, 0.f));
                __half2 h1 = __floats2half2_rn(fmaxf(c[2] + b0, 0.f),
                                               fmaxf(c[3] + b1, 0.f));
                *(__half2*)(smb + SM_X2 + row0 * XPITCH + col * 2) = h0;
                *(__half2*)(smb + SM_X2 + (row0 + 8) * XPITCH + col * 2) = h1;
            }
        }
    } else {
        float* red = (float*)(smb + SM_WB);
#pragma unroll
        for (int nt = 0; nt < 16; nt++) {
            int col = wn + nt * 8 + (lane & 3) * 2;
            float b0 = __ldg(bias + col), b1 = __ldg(bias + col + 1);
            float t0 = 0.f, t1 = 0.f;
#pragma unroll
            for (int mt = 0; mt < 2; mt++) {
                float* c = acc[mt][nt];
                t0 += fmaxf(c[0] + b0, 0.f) + fmaxf(c[2] + b0, 0.f);
                t1 += fmaxf(c[1] + b1, 0.f) + fmaxf(c[3] + b1, 0.f);
            }
#pragma unroll
            for (int d = 4; d < 32; d <<= 1) {
                t0 += __shfl_xor_sync(FULLMASK, t0, d);
                t1 += __shfl_xor_sync(FULLMASK, t1, d);
            }
            if (lane < 4) {
                red[(w >> 2) * 512 + col] = t0;
                red[(w >> 2) * 512 + col + 1] = t1;
            }
        }
    }
}

__global__ void __launch_bounds__(256, 1)
main_kernel(const float* __restrict__ input, const float* __restrict__ b2,
            const float* __restrict__ b3) {
    extern __shared__ __align__(16) char sm[];
    const uint32_t smem = (uint32_t)__cvta_generic_to_shared(sm);
    const int tid = threadIdx.x;
    const int b = blockIdx.x >> 6, i = blockIdx.x & 63;

    stageW(g_W2t, 0, smem, tid);
    stageW(g_W2t, 1, smem, tid);

    float* xin = (float*)(sm + SM_X2);
#pragma unroll
    for (int s = 0; s < 2; s++) {
        int idx = tid + s * 256;
        xin[idx] = input[(size_t)((b * 64 + i) << 9) + idx];
    }
    __syncthreads();

    // h1: X1[r][c] = relu(g_A[b*64+r][c] + sum_m xin[8r+m]*Rt[m][c]), f16
    {
        const int c0 = tid * 2;
        float r0[8], r1[8];
#pragma unroll
        for (int m = 0; m < 8; m++) {
            r0[m] = g_Rt[m * 512 + c0];
            r1[m] = g_Rt[m * 512 + c0 + 1];
        }
#pragma unroll 4
        for (int r = 0; r < 64; r++) {
            const float* xr = xin + 8 * r;
            float2 a = *(const float2*)(g_A + ((size_t)(b * 64 + r) << 9) + c0);
            float s0 = a.x, s1 = a.y;
#pragma unroll
            for (int m = 0; m < 8; m++) {
                float x = xr[m];
                s0 = fmaf(x, r0[m], s0);
                s1 = fmaf(x, r1[m], s1);
            }
            *(__half2*)(sm + SM_X1 + r * XPITCH + tid * 4) =
                __floats2half2_rn(fmaxf(s0, 0.f), fmaxf(s1, 0.f));
        }
    }
    // gemm loop's first sync covers X1 visibility
    gemm_layer<false>(sm, smem, smem + SM_X1, g_W2t, g_W3t, b2, tid);
    gemm_layer<true >(sm, smem, smem + SM_X2, g_W3t, nullptr, b3, tid);
    __syncthreads();
    float* red = (float*)(sm + SM_WB);
#pragma unroll
    for (int oo = 0; oo < 2; oo++) {
        int col = tid + 256 * oo;
        g_partial[(size_t)blockIdx.x * 512 + col] = red[col] + red[512 + col];
    }
}

// fp32 W[o][k] -> f16 Wt[k][o]
__global__ void prep_wt_kernel(const float* __restrict__ W, __half* __restrict__ Wt) {
    __shared__ float t[32][33];
    int k = blockIdx.x * 32 + threadIdx.x;
    int o0 = blockIdx.y * 32;
#pragma unroll
    for (int s = 0; s < 32; s += 8)
        t[threadIdx.y + s][threadIdx.x] = W[(size_t)(o0 + threadIdx.y + s) * 512 + k];
    __syncthreads();
    int o = o0 + threadIdx.x;
    int k0 = blockIdx.x * 32;
#pragma unroll
    for (int s = 0; s < 32; s += 8)
        Wt[(size_t)(k0 + threadIdx.y + s) * 512 + o] =
            __float2half(t[threadIdx.x][threadIdx.y + s]);
}

__global__ void prep_a_kernel(const float* __restrict__ X,
                              const float* __restrict__ W1,
                              const float* __restrict__ b1) {
    __shared__ float As[16][68];
    __shared__ float Bs[16][68];
    const int tid = threadIdx.x;
    const int row0 = blockIdx.x * 64, col0 = blockIdx.y * 64;
    const int tx = tid & 15, ty = tid >> 4;
    float acc[4][4] = {};
    for (int kc = 0; kc < 32; kc++) {
#pragma unroll
        for (int s = 0; s < 4; s++) {
            int idx = tid + s * 256;
            int m = idx >> 4, kk = idx & 15;
            As[kk][m] = X[(row0 + m) * 512 + kc * 16 + kk];
            Bs[kk][m] = W1[(col0 + m) * 1024 + kc * 16 + kk];
        }
        __syncthreads();
#pragma unroll
        for (int kk = 0; kk < 16; kk++) {
            float a[4], bb[4];
#pragma unroll
            for (int u = 0; u < 4; u++) a[u] = As[kk][ty * 4 + u];
#pragma unroll
            for (int u = 0; u < 4; u++) bb[u] = Bs[kk][tx * 4 + u];
#pragma unroll
            for (int u = 0; u < 4; u++)
#pragma unroll
                for (int v = 0; v < 4; v++)
                    acc[u][v] = fmaf(a[u], bb[v], acc[u][v]);
        }
        __syncthreads();
    }
#pragma unroll
    for (int u = 0; u < 4; u++) {
        int row = row0 + ty * 4 + u;
#pragma unroll
        for (int v = 0; v < 4; v++) {
            int o = col0 + tx * 4 + v;
            g_A[row * 512 + o] = acc[u][v] + b1[o];
        }
    }
}

__global__ void prep_r_kernel(const float* __restrict__ W1) {
    int o = threadIdx.x, m = blockIdx.x;
    const float* p = W1 + o * 1024 + 512 + m * 64;
    float s = 0.f;
#pragma unroll
    for (int t = 0; t < 64; t++) s += p[t];
    g_Rt[m * 512 + o] = s;
}

__global__ void reduce_sent_kernel() {
    int b = blockIdx.x, o = threadIdx.x;
    const float* p = g_partial + (size_t)b * 64 * 512 + o;
    float s = 0.f;
#pragma unroll 8
    for (int q = 0; q < 64; q++) s += p[q * 512];
    g_emb[b * 1024 + o] = s * (1.0f / 4096.0f);
}

__global__ void im_gemm_kernel(const float* __restrict__ imx,
                               const float* __restrict__ imw,
                               const float* __restrict__ imb) {
    int gw = (blockIdx.x * blockDim.x + threadIdx.x) >> 5;
    int lane = threadIdx.x & 31;
    int bi = gw >> 9, o = gw & 511;
    const float* x = imx + bi * 2048;
    const float* wv = imw + o * 2048;
    float s = 0.f;
    for (int k = lane; k < 2048; k += 32) s = fmaf(x[k], wv[k], s);
#pragma unroll
    for (int d = 16; d; d >>= 1) s += __shfl_xor_sync(FULLMASK, s, d);
    if (lane == 0) g_img[bi * 512 + o] = s + imb[o];
}

__global__ void bn_relu_kernel(const float* __restrict__ gamma,
                               const float* __restrict__ beta) {
    int o = threadIdx.x;
    float v[16], mu = 0.f;
#pragma unroll
    for (int bi = 0; bi < 16; bi++) { v[bi] = g_img[bi * 512 + o]; mu += v[bi]; }
    mu *= (1.f / 16.f);
    float var = 0.f;
#pragma unroll
    for (int bi = 0; bi < 16; bi++) { float d = v[bi] - mu; var = fmaf(d, d, var); }
    var *= (1.f / 16.f);
    float inv = rsqrtf(var + 1e-5f);
    float g = gamma[o], be = beta[o];
#pragma unroll
    for (int bi = 0; bi < 16; bi++) {
        float y = fmaf(g * (v[bi] - mu), inv, be);
        g_emb[bi * 1024 + 512 + o] = fmaxf(y, 0.f);
    }
}

__global__ void head1_kernel(const float* __restrict__ d1w,
                             const float* __restrict__ d1b) {
    int gw = (blockIdx.x * blockDim.x + threadIdx.x) >> 5;
    int lane = threadIdx.x & 31;
    int bi = gw >> 9, o = gw & 511;
    const float* e = g_emb + bi * 1024;
    const float* wv = d1w + o * 1024;
    float s = 0.f;
    for (int k = lane; k < 1024; k += 32) s = fmaf(e[k], wv[k], s);
#pragma unroll
    for (int d = 16; d; d >>= 1) s += __shfl_xor_sync(FULLMASK, s, d);
    if (lane == 0) g_hidden[bi * 512 + o] = fmaxf(s + d1b[o], 0.f);
}

__global__ void head2_kernel(const float* __restrict__ d2w,
                             const float* __restrict__ d2b,
                             float* __restrict__ out) {
    int gw = threadIdx.x >> 5, lane = threadIdx.x & 31;
    int bi = gw >> 1, q = gw & 1;
    const float* h = g_hidden + bi * 512;
    const float* wv = d2w + q * 512;
    float s = 0.f;
    for (int k = lane; k < 512; k += 32) s = fmaf(h[k], wv[k], s);
#pragma unroll
    for (int d = 16; d; d >>= 1) s += __shfl_xor_sync(FULLMASK, s, d);
    if (lane == 0) out[bi * 2 + q] = s + d2b[q];
}

extern "C" void kernel_launch(void* const* d_in, const int* in_sizes, int n_in,
                              void* d_out, int out_size) {
    const float* input = (const float*)d_in[0];
    const float* im_input = (const float*)d_in[1];
    const float* g1w = (const float*)d_in[2];
    const float* g1b = (const float*)d_in[3];
    const float* g2w = (const float*)d_in[4];
    const float* g2b = (const float*)d_in[5];
    const float* g3w = (const float*)d_in[6];
    const float* g3b = (const float*)d_in[7];
    const float* imw = (const float*)d_in[8];
    const float* imb = (const float*)d_in[9];
    const float* gam = (const float*)d_in[10];
    const float* bet = (const float*)d_in[11];
    const float* d1w = (const float*)d_in[12];
    const float* d1b = (const float*)d_in[13];
    const float* d2w = (const float*)d_in[14];
    const float* d2b = (const float*)d_in[15];
    float* out = (float*)d_out;

    cudaFuncSetAttribute(main_kernel,
                         cudaFuncAttributeMaxDynamicSharedMemorySize, SMEM_TOTAL);

    __half* w2t; cudaGetSymbolAddress((void**)&w2t, g_W2t);
    __half* w3t; cudaGetSymbolAddress((void**)&w3t, g_W3t);

    prep_a_kernel<<<dim3(16, 8), 256>>>(input, g1w, g1b);
    prep_r_kernel<<<8, 512>>>(g1w);
    prep_wt_kernel<<<dim3(16, 16), dim3(32, 8)>>>(g2w, w2t);
    prep_wt_kernel<<<dim3(16, 16), dim3(32, 8)>>>(g3w, w3t);
    main_kernel<<<1024, 256, SMEM_TOTAL>>>(input, g2b, g3b);
    reduce_sent_kernel<<<16, 512>>>();
    im_gemm_kernel<<<1024, 256>>>(im_input, imw, imb);
    bn_relu_kernel<<<1, 512>>>(gam, bet);
    head1_kernel<<<1024, 256>>>(d1w, d1b);
    head2_kernel<<<1, 1024>>>(d2w, d2b, out);
}

// round 10
// speedup vs baseline: 8.0585x; 1.0008x over previous
#include <cuda_runtime.h>
#include <cuda_fp16.h>
#include <cstdint>

#define FULLMASK 0xFFFFFFFFu

__device__ float  g_A[1024 * 512];
__device__ float  g_Rt[8 * 512];
__device__ __half g_W2t[512 * 512];   // f16, transposed: [k][o]
__device__ __half g_W3t[512 * 512];
__device__ float  g_partial[1024 * 512];
__device__ float  g_img[16 * 512];
__device__ float  g_emb[16 * 1024];
__device__ float  g_hidden[16 * 512];

// smem (bytes): X [64][520]f16 (in-place for both layers), 3x W stage [16][520]f16
#define XPITCH 1040
#define SM_X1 0
#define SM_WB 66560
#define WBSZ  16640
#define SMEM_TOTAL 116480

__device__ __forceinline__ void ldsm4(uint32_t* r, uint32_t a) {
    asm volatile("ldmatrix.sync.aligned.m8n8.x4.shared.b16 {%0,%1,%2,%3}, [%4];"
                 : "=r"(r[0]), "=r"(r[1]), "=r"(r[2]), "=r"(r[3]) : "r"(a));
}
__device__ __forceinline__ void ldsm4t(uint32_t* r, uint32_t a) {
    asm volatile("ldmatrix.sync.aligned.m8n8.x4.trans.shared.b16 {%0,%1,%2,%3}, [%4];"
                 : "=r"(r[0]), "=r"(r[1]), "=r"(r[2]), "=r"(r[3]) : "r"(a));
}
__device__ __forceinline__ void mma16816(float* c, const uint32_t* a,
                                         uint32_t b0, uint32_t b1) {
    asm volatile(
        "mma.sync.aligned.m16n8k16.row.col.f32.f16.f16.f32 "
        "{%0,%1,%2,%3}, {%4,%5,%6,%7}, {%8,%9}, {%0,%1,%2,%3};"
        : "+f"(c[0]), "+f"(c[1]), "+f"(c[2]), "+f"(c[3])
        : "r"(a[0]), "r"(a[1]), "r"(a[2]), "r"(a[3]), "r"(b0), "r"(b1));
}

// stage 16 k-rows of Wt[k][512] f16 into ring buffer s%3 (512 threads)
__device__ __forceinline__ void stageW(const __half* Wt, int s, uint32_t smem,
                                       int tid) {
    const char* src = (const char*)(Wt + (size_t)s * 16 * 512);
    uint32_t dst = smem + SM_WB + (s % 3) * WBSZ;
#pragma unroll
    for (int q = 0; q < 2; q++) {
        int idx = tid + q * 512;
        int row = idx >> 6, c = idx & 63;
        asm volatile("cp.async.cg.shared.global [%0], [%1], 16;"
                     :: "r"(dst + row * XPITCH + c * 16),
                        "l"(src + row * 1024 + c * 16));
    }
    asm volatile("cp.async.commit_group;" ::: "memory");
}

// C[64x512] = X(smem f16) * W(streamed). !LAST: relu->f16 back into X (in place,
// after mainloop). LAST: column sums -> red at SM_WB + 2*WBSZ.
template <bool LAST>
__device__ __forceinline__ void gemm_layer(char* smb, uint32_t smem,
                                           const __half* Wt, const __half* nextWt,
                                           const float* __restrict__ bias, int tid) {
    const int lane = tid & 31, w = tid >> 5;
    const int wr = w >> 2;              // 0..3  M group of 16
    const int wn = (w & 3) * 128;       // N group of 128
    float acc[16][4];
#pragma unroll
    for (int nt = 0; nt < 16; nt++)
#pragma unroll
        for (int e = 0; e < 4; e++) acc[nt][e] = 0.f;

    const uint32_t aAddr = smem + SM_X1 + (wr * 16 + (lane & 15)) * XPITCH
                           + (lane >> 4) * 16;
    const uint32_t bOff = (lane & 15) * XPITCH + (lane >> 4) * 16 + wn * 2;

#pragma unroll 1
    for (int s = 0; s < 32; s++) {
        if (s < 31) asm volatile("cp.async.wait_group 1;" ::: "memory");
        else        asm volatile("cp.async.wait_group 0;" ::: "memory");
        __syncthreads();
        uint32_t bb = smem + SM_WB + (s % 3) * WBSZ + bOff;
        uint32_t a[4];
        ldsm4(a, aAddr + s * 32);
        uint32_t bf[2][4];
        ldsm4t(bf[0], bb);
#pragma unroll
        for (int ng = 0; ng < 8; ng++) {
            if (ng < 7) ldsm4t(bf[(ng + 1) & 1], bb + (ng + 1) * 32);
            const uint32_t* f = bf[ng & 1];
            mma16816(acc[2 * ng],     a, f[0], f[1]);
            mma16816(acc[2 * ng + 1], a, f[2], f[3]);
        }
        if (s + 2 < 32) stageW(Wt, s + 2, smem, tid);
    }
    __syncthreads();
    if (nextWt) { stageW(nextWt, 0, smem, tid); stageW(nextWt, 1, smem, tid); }

    if (!LAST) {
        int row0 = wr * 16 + (lane >> 2);
#pragma unroll
        for (int nt = 0; nt < 16; nt++) {
            int col = wn + nt * 8 + (lane & 3) * 2;
            float b0 = __ldg(bias + col), b1 = __ldg(bias + col + 1);
            float* c = acc[nt];
            __half2 h0 = __floats2half2_rn(fmaxf(c[0] + b0, 0.f),
                                           fmaxf(c[1] + b1, 0.f));
            __half2 h1 = __floats2half2_rn(fmaxf(c[2] + b0, 0.f),
                                           fmaxf(c[3] + b1, 0.f));
            *(__half2*)(smb + SM_X1 + row0 * XPITCH + col * 2) = h0;
            *(__half2*)(smb + SM_X1 + (row0 + 8) * XPITCH + col * 2) = h1;
        }
    } else {
        float* red = (float*)(smb + SM_WB + 2 * WBSZ);
#pragma unroll
        for (int nt = 0; nt < 16; nt++) {
            int col = wn + nt * 8 + (lane & 3) * 2;
            float b0 = __ldg(bias + col), b1 = __ldg(bias + col + 1);
            float* c = acc[nt];
            float t0 = fmaxf(c[0] + b0, 0.f) + fmaxf(c[2] + b0, 0.f);
            float t1 = fmaxf(c[1] + b1, 0.f) + fmaxf(c[3] + b1, 0.f);
#pragma unroll
            for (int d = 4; d < 32; d <<= 1) {
                t0 += __shfl_xor_sync(FULLMASK, t0, d);
                t1 += __shfl_xor_sync(FULLMASK, t1, d);
            }
            if (lane < 4) {
                red[wr * 512 + col] = t0;
                red[wr * 512 + col + 1] = t1;
            }
        }
    }
}

__global__ void __launch_bounds__(512, 1)
main_kernel(const float* __restrict__ input, const float* __restrict__ b2,
            const float* __restrict__ b3) {
    extern __shared__ __align__(16) char sm[];
    const uint32_t smem = (uint32_t)__cvta_generic_to_shared(sm);
    const int tid = threadIdx.x;
    const int b = blockIdx.x >> 6, i = blockIdx.x & 63;

    stageW(g_W2t, 0, smem, tid);
    stageW(g_W2t, 1, smem, tid);

    float* xin = (float*)(sm + SM_WB + 2 * WBSZ);   // slot2 free until stage s=2
    xin[tid] = input[(size_t)((b * 64 + i) << 9) + tid];
    __syncthreads();

    // h1: X[r][c] = relu(g_A[b*64+r][c] + sum_m xin[8r+m]*Rt[m][c]), f16
    {
        const int c0 = (tid & 255) * 2;
        const int rbase = (tid >> 8) * 32;
        float r0[8], r1[8];
#pragma unroll
        for (int m = 0; m < 8; m++) {
            r0[m] = g_Rt[m * 512 + c0];
            r1[m] = g_Rt[m * 512 + c0 + 1];
        }
#pragma unroll 4
        for (int rr = 0; rr < 32; rr++) {
            int r = rbase + rr;
            const float* xr = xin + 8 * r;
            float2 a = *(const float2*)(g_A + ((size_t)(b * 64 + r) << 9) + c0);
            float s0 = a.x, s1 = a.y;
#pragma unroll
            for (int m = 0; m < 8; m++) {
                float x = xr[m];
                s0 = fmaf(x, r0[m], s0);
                s1 = fmaf(x, r1[m], s1);
            }
            *(__half2*)(sm + SM_X1 + r * XPITCH + c0 * 2) =
                __floats2half2_rn(fmaxf(s0, 0.f), fmaxf(s1, 0.f));
        }
    }
    // gemm loop's first __syncthreads covers X visibility (and xin death)
    gemm_layer<false>(sm, smem, g_W2t, g_W3t, b2, tid);
    gemm_layer<true >(sm, smem, g_W3t, nullptr, b3, tid);
    __syncthreads();
    float* red = (float*)(sm + SM_WB + 2 * WBSZ);
    {
        int col = tid;
        g_partial[(size_t)blockIdx.x * 512 + col] =
            red[col] + red[512 + col] + red[1024 + col] + red[1536 + col];
    }
}

// fp32 W[o][k] -> f16 Wt[k][o]
__global__ void prep_wt_kernel(const float* __restrict__ W, __half* __restrict__ Wt) {
    __shared__ float t[32][33];
    int k = blockIdx.x * 32 + threadIdx.x;
    int o0 = blockIdx.y * 32;
#pragma unroll
    for (int s = 0; s < 32; s += 8)
        t[threadIdx.y + s][threadIdx.x] = W[(size_t)(o0 + threadIdx.y + s) * 512 + k];
    __syncthreads();
    int o = o0 + threadIdx.x;
    int k0 = blockIdx.x * 32;
#pragma unroll
    for (int s = 0; s < 32; s += 8)
        Wt[(size_t)(k0 + threadIdx.y + s) * 512 + o] =
            __float2half(t[threadIdx.x][threadIdx.y + s]);
}

__global__ void prep_a_kernel(const float* __restrict__ X,
                              const float* __restrict__ W1,
                              const float* __restrict__ b1) {
    __shared__ float As[16][68];
    __shared__ float Bs[16][68];
    const int tid = threadIdx.x;
    const int row0 = blockIdx.x * 64, col0 = blockIdx.y * 64;
    const int tx = tid & 15, ty = tid >> 4;
    float acc[4][4] = {};
    for (int kc = 0; kc < 32; kc++) {
#pragma unroll
        for (int s = 0; s < 4; s++) {
            int idx = tid + s * 256;
            int m = idx >> 4, kk = idx & 15;
            As[kk][m] = X[(row0 + m) * 512 + kc * 16 + kk];
            Bs[kk][m] = W1[(col0 + m) * 1024 + kc * 16 + kk];
        }
        __syncthreads();
#pragma unroll
        for (int kk = 0; kk < 16; kk++) {
            float a[4], bb[4];
#pragma unroll
            for (int u = 0; u < 4; u++) a[u] = As[kk][ty * 4 + u];
#pragma unroll
            for (int u = 0; u < 4; u++) bb[u] = Bs[kk][tx * 4 + u];
#pragma unroll
            for (int u = 0; u < 4; u++)
#pragma unroll
                for (int v = 0; v < 4; v++)
                    acc[u][v] = fmaf(a[u], bb[v], acc[u][v]);
        }
        __syncthreads();
    }
#pragma unroll
    for (int u = 0; u < 4; u++) {
        int row = row0 + ty * 4 + u;
#pragma unroll
        for (int v = 0; v < 4; v++) {
            int o = col0 + tx * 4 + v;
            g_A[row * 512 + o] = acc[u][v] + b1[o];
        }
    }
}

__global__ void prep_r_kernel(const float* __restrict__ W1) {
    int o = threadIdx.x, m = blockIdx.x;
    const float* p = W1 + o * 1024 + 512 + m * 64;
    float s = 0.f;
#pragma unroll
    for (int t = 0; t < 64; t++) s += p[t];
    g_Rt[m * 512 + o] = s;
}

__global__ void reduce_sent_kernel() {
    int b = blockIdx.x, o = threadIdx.x;
    const float* p = g_partial + (size_t)b * 64 * 512 + o;
    float s = 0.f;
#pragma unroll 8
    for (int q = 0; q < 64; q++) s += p[q * 512];
    g_emb[b * 1024 + o] = s * (1.0f / 4096.0f);
}

__global__ void im_gemm_kernel(const float* __restrict__ imx,
                               const float* __restrict__ imw,
                               const float* __restrict__ imb) {
    int gw = (blockIdx.x * blockDim.x + threadIdx.x) >> 5;
    int lane = threadIdx.x & 31;
    int bi = gw >> 9, o = gw & 511;
    const float* x = imx + bi * 2048;
    const float* wv = imw + o * 2048;
    float s = 0.f;
    for (int k = lane; k < 2048; k += 32) s = fmaf(x[k], wv[k], s);
#pragma unroll
    for (int d = 16; d; d >>= 1) s += __shfl_xor_sync(FULLMASK, s, d);
    if (lane == 0) g_img[bi * 512 + o] = s + imb[o];
}

__global__ void bn_relu_kernel(const float* __restrict__ gamma,
                               const float* __restrict__ beta) {
    int o = threadIdx.x;
    float v[16], mu = 0.f;
#pragma unroll
    for (int bi = 0; bi < 16; bi++) { v[bi] = g_img[bi * 512 + o]; mu += v[bi]; }
    mu *= (1.f / 16.f);
    float var = 0.f;
#pragma unroll
    for (int bi = 0; bi < 16; bi++) { float d = v[bi] - mu; var = fmaf(d, d, var); }
    var *= (1.f / 16.f);
    float inv = rsqrtf(var + 1e-5f);
    float g = gamma[o], be = beta[o];
#pragma unroll
    for (int bi = 0; bi < 16; bi++) {
        float y = fmaf(g * (v[bi] - mu), inv, be);
        g_emb[bi * 1024 + 512 + o] = fmaxf(y, 0.f);
    }
}

__global__ void head1_kernel(const float* __restrict__ d1w,
                             const float* __restrict__ d1b) {
    int gw = (blockIdx.x * blockDim.x + threadIdx.x) >> 5;
    int lane = threadIdx.x & 31;
    int bi = gw >> 9, o = gw & 511;
    const float* e = g_emb + bi * 1024;
    const float* wv = d1w + o * 1024;
    float s = 0.f;
    for (int k = lane; k < 1024; k += 32) s = fmaf(e[k], wv[k], s);
#pragma unroll
    for (int d = 16; d; d >>= 1) s += __shfl_xor_sync(FULLMASK, s, d);
    if (lane == 0) g_hidden[bi * 512 + o] = fmaxf(s + d1b[o], 0.f);
}

__global__ void head2_kernel(const float* __restrict__ d2w,
                             const float* __restrict__ d2b,
                             float* __restrict__ out) {
    int gw = threadIdx.x >> 5, lane = threadIdx.x & 31;
    int bi = gw >> 1, q = gw & 1;
    const float* h = g_hidden + bi * 512;
    const float* wv = d2w + q * 512;
    float s = 0.f;
    for (int k = lane; k < 512; k += 32) s = fmaf(h[k], wv[k], s);
#pragma unroll
    for (int d = 16; d; d >>= 1) s += __shfl_xor_sync(FULLMASK, s, d);
    if (lane == 0) out[bi * 2 + q] = s + d2b[q];
}

extern "C" void kernel_launch(void* const* d_in, const int* in_sizes, int n_in,
                              void* d_out, int out_size) {
    const float* input = (const float*)d_in[0];
    const float* im_input = (const float*)d_in[1];
    const float* g1w = (const float*)d_in[2];
    const float* g1b = (const float*)d_in[3];
    const float* g2w = (const float*)d_in[4];
    const float* g2b = (const float*)d_in[5];
    const float* g3w = (const float*)d_in[6];
    const float* g3b = (const float*)d_in[7];
    const float* imw = (const float*)d_in[8];
    const float* imb = (const float*)d_in[9];
    const float* gam = (const float*)d_in[10];
    const float* bet = (const float*)d_in[11];
    const float* d1w = (const float*)d_in[12];
    const float* d1b = (const float*)d_in[13];
    const float* d2w = (const float*)d_in[14];
    const float* d2b = (const float*)d_in[15];
    float* out = (float*)d_out;

    cudaFuncSetAttribute(main_kernel,
                         cudaFuncAttributeMaxDynamicSharedMemorySize, SMEM_TOTAL);

    __half* w2t; cudaGetSymbolAddress((void**)&w2t, g_W2t);
    __half* w3t; cudaGetSymbolAddress((void**)&w3t, g_W3t);

    prep_a_kernel<<<dim3(16, 8), 256>>>(input, g1w, g1b);
    prep_r_kernel<<<8, 512>>>(g1w);
    prep_wt_kernel<<<dim3(16, 16), dim3(32, 8)>>>(g2w, w2t);
    prep_wt_kernel<<<dim3(16, 16), dim3(32, 8)>>>(g3w, w3t);
    main_kernel<<<1024, 512, SMEM_TOTAL>>>(input, g2b, g3b);
    reduce_sent_kernel<<<16, 512>>>();
    im_gemm_kernel<<<1024, 256>>>(im_input, imw, imb);
    bn_relu_kernel<<<1, 512>>>(gam, bet);
    head1_kernel<<<1024, 256>>>(d1w, d1b);
    head2_kernel<<<1, 1024>>>(d2w, d2b, out);
}